// round 1
// baseline (speedup 1.0000x reference)
#include <cuda_runtime.h>
#include <math.h>

#define B_  2
#define N_  2048
#define C_  1024
#define H_  16
#define DH_ 64
#define M_  (B_*N_)     // 4096 rows
#define BH_ (B_*H_)     // 32 head-batches

// Scratch (device globals: allocation-guard safe). 16MB each.
__device__ float g_q [BH_ * N_ * DH_];
__device__ float g_k [BH_ * N_ * DH_];
__device__ float g_v [BH_ * N_ * DH_];
__device__ float g_ao[M_ * C_];

// inv_freq[i] = 100^(-i/16)  (fp32-exact table)
__constant__ float c_invf[16] = {
    1.0f,
    0.7498942093324559f,
    0.5623413251903491f,
    0.4216965034285822f,
    0.31622776601683794f,
    0.23713737056616552f,
    0.1778279410038923f,
    0.13335214321633237f,
    0.1f,
    0.07498942093324558f,
    0.05623413251903491f,
    0.04216965034285822f,
    0.031622776601683794f,
    0.023713737056616552f,
    0.01778279410038923f,
    0.013335214321633237f
};

// ---------------------------------------------------------------------------
// Kernel A: qkv = x @ qkv_w^T  (M=4096, N=3072, K=1024), fused 2D-RoPE on q,k,
// scatter to [B,H,N,Dh].
// 128x128 tile, BK=16, 256 threads, 8x8 microtile.
// ---------------------------------------------------------------------------
__global__ __launch_bounds__(256) void qkv_rope_kernel(
    const float* __restrict__ x, const float* __restrict__ w,
    const int* __restrict__ pos)
{
    __shared__ float At[16][132];   // [k][row], padded stride (mult of 4)
    __shared__ float Bt[16][132];

    const int tid = threadIdx.x;
    const int tx  = tid & 15;       // 0..15 -> 8 output cols each
    const int ty  = tid >> 4;       // 0..15 -> 8 output rows each
    const int m0  = blockIdx.y * 128;
    const int n0  = blockIdx.x * 128;

    float acc[8][8];
#pragma unroll
    for (int i = 0; i < 8; i++)
#pragma unroll
        for (int j = 0; j < 8; j++) acc[i][j] = 0.f;

    const int lkq  = (tid & 3) * 4;   // k offset 0,4,8,12
    const int lrow = tid >> 2;        // 0..63 (+64 on second pass)

    for (int k0 = 0; k0 < C_; k0 += 16) {
#pragma unroll
        for (int s = 0; s < 2; s++) {
            int row = lrow + s * 64;
            float4 a4 = *(const float4*)&x[(size_t)(m0 + row) * C_ + k0 + lkq];
            At[lkq+0][row] = a4.x; At[lkq+1][row] = a4.y;
            At[lkq+2][row] = a4.z; At[lkq+3][row] = a4.w;
            float4 b4 = *(const float4*)&w[(size_t)(n0 + row) * C_ + k0 + lkq];
            Bt[lkq+0][row] = b4.x; Bt[lkq+1][row] = b4.y;
            Bt[lkq+2][row] = b4.z; Bt[lkq+3][row] = b4.w;
        }
        __syncthreads();
#pragma unroll
        for (int kk = 0; kk < 16; kk++) {
            float a[8], b[8];
            *(float4*)&a[0] = *(const float4*)&At[kk][ty*8];
            *(float4*)&a[4] = *(const float4*)&At[kk][ty*8+4];
            *(float4*)&b[0] = *(const float4*)&Bt[kk][tx*8];
            *(float4*)&b[4] = *(const float4*)&Bt[kk][tx*8+4];
#pragma unroll
            for (int i = 0; i < 8; i++)
#pragma unroll
                for (int j = 0; j < 8; j++)
                    acc[i][j] = fmaf(a[i], b[j], acc[i][j]);
        }
        __syncthreads();
    }

    // ---- epilogue: RoPE (q,k) + scatter ----
    const int which = n0 >> 10;               // 0=q, 1=k, 2=v (uniform per block)
    const int cbase = n0 & 1023;
    const int h  = (cbase + tx * 8) >> 6;     // head (uniform per thread)
    const int d0 = (tx * 8) & 63;             // Dh offset (8 consecutive dims)
    float* dst = (which == 0) ? g_q : (which == 1) ? g_k : g_v;

#pragma unroll
    for (int i = 0; i < 8; i++) {
        int m   = m0 + ty * 8 + i;
        int b   = m >> 11;
        int tok = m & 2047;
        float out[8];
        if (which == 2) {
#pragma unroll
            for (int j = 0; j < 8; j++) out[j] = acc[i][j];
        } else {
            float py = (float)pos[(size_t)m * 2 + 0];
            float px = (float)pos[(size_t)m * 2 + 1];
#pragma unroll
            for (int j = 0; j < 8; j++) {
                // rotation partner lives at dim d^16 == lane tx^2, same j
                float partner = __shfl_xor_sync(0xffffffffu, acc[i][j], 2);
                int d  = d0 + j;
                int dd = d & 31;
                float p   = (d & 32) ? px : py;
                float ang = p * c_invf[dd & 15];
                float sv, cv;
                sincosf(ang, &sv, &cv);
                out[j] = (dd < 16) ? (acc[i][j] * cv - partner * sv)
                                   : (partner   * sv + acc[i][j] * cv);
            }
        }
        float* o = dst + (((size_t)(b * 16 + h) * 2048 + tok) << 6) + d0;
        *(float4*)&o[0] = *(const float4*)&out[0];
        *(float4*)&o[4] = *(const float4*)&out[4];
    }
}

// ---------------------------------------------------------------------------
// Kernel B: flash attention. One block = 64 q-rows of one (b,h).
// 128 threads: tx 0..15 (4 cols), ty 0..7 (8 rows). Online softmax.
// ---------------------------------------------------------------------------
__global__ __launch_bounds__(128) void attn_kernel()
{
    extern __shared__ float sm[];
    float* Qt   = sm;                 // [64][68]  (transposed: [dim][row])
    float* Kt   = Qt + 64 * 68;       // [64][68]  ([dim][kvcol])
    float* Vs   = Kt + 64 * 68;       // [64][68]  ([kvrow][dim])
    float* St   = Vs + 64 * 68;       // [64][68]  (transposed: [kvcol][qrow])
    float* mrow = St + 64 * 68;       // [64]
    float* lrow = mrow + 64;          // [64]
    float* arow = lrow + 64;          // [64]

    const int tid = threadIdx.x;
    const int tx  = tid & 15;
    const int ty  = tid >> 4;
    const int bh  = blockIdx.y;
    const int q0  = blockIdx.x * 64;

    const float* Q = g_q + ((size_t)bh * N_ + q0) * DH_;
    const float* K = g_k + (size_t)bh * N_ * DH_;
    const float* V = g_v + (size_t)bh * N_ * DH_;

    // load Q tile transposed
#pragma unroll
    for (int s = 0; s < 8; s++) {
        int f  = tid + s * 128;
        int dq = (f & 15) * 4;
        int r  = f >> 4;
        float4 v4 = *(const float4*)&Q[(size_t)r * DH_ + dq];
        Qt[(dq+0)*68 + r] = v4.x; Qt[(dq+1)*68 + r] = v4.y;
        Qt[(dq+2)*68 + r] = v4.z; Qt[(dq+3)*68 + r] = v4.w;
    }
    if (tid < 64) { mrow[tid] = -1e30f; lrow[tid] = 0.f; }

    float acc[8][4];
#pragma unroll
    for (int i = 0; i < 8; i++)
#pragma unroll
        for (int j = 0; j < 4; j++) acc[i][j] = 0.f;

    for (int kv0 = 0; kv0 < N_; kv0 += 64) {
        __syncthreads();   // protects Kt/Vs reuse + Qt/mrow init on iter 0
#pragma unroll
        for (int s = 0; s < 8; s++) {
            int f  = tid + s * 128;
            int dq = (f & 15) * 4;
            int r  = f >> 4;
            float4 k4 = *(const float4*)&K[(size_t)(kv0 + r) * DH_ + dq];
            Kt[(dq+0)*68 + r] = k4.x; Kt[(dq+1)*68 + r] = k4.y;
            Kt[(dq+2)*68 + r] = k4.z; Kt[(dq+3)*68 + r] = k4.w;
            float4 v4 = *(const float4*)&V[(size_t)(kv0 + r) * DH_ + dq];
            *(float4*)&Vs[r*68 + dq] = v4;
        }
        __syncthreads();

        // S = scale * Q K^T  -> St[c][r]
        float s8[8][4];
#pragma unroll
        for (int i = 0; i < 8; i++)
#pragma unroll
            for (int j = 0; j < 4; j++) s8[i][j] = 0.f;
#pragma unroll 8
        for (int kk = 0; kk < 64; kk++) {
            float a[8], b[4];
            *(float4*)&a[0] = *(const float4*)&Qt[kk*68 + ty*8];
            *(float4*)&a[4] = *(const float4*)&Qt[kk*68 + ty*8+4];
            *(float4*)&b[0] = *(const float4*)&Kt[kk*68 + tx*4];
#pragma unroll
            for (int i = 0; i < 8; i++)
#pragma unroll
                for (int j = 0; j < 4; j++)
                    s8[i][j] = fmaf(a[i], b[j], s8[i][j]);
        }
#pragma unroll
        for (int i = 0; i < 8; i++)
#pragma unroll
            for (int j = 0; j < 4; j++)
                St[(tx*4+j)*68 + ty*8+i] = s8[i][j] * 0.125f;
        __syncthreads();

        // online softmax, one thread per q-row
        if (tid < 64) {
            int r = tid;
            float mold = mrow[r];
            float mx = mold;
#pragma unroll 8
            for (int c = 0; c < 64; c++) mx = fmaxf(mx, St[c*68 + r]);
            float alpha = __expf(mold - mx);
            float sum = 0.f;
#pragma unroll 8
            for (int c = 0; c < 64; c++) {
                float pv = __expf(St[c*68 + r] - mx);
                St[c*68 + r] = pv;
                sum += pv;
            }
            mrow[r] = mx;
            lrow[r] = lrow[r] * alpha + sum;
            arow[r] = alpha;
        }
        __syncthreads();

        // O = O*alpha + P V
#pragma unroll
        for (int i = 0; i < 8; i++) {
            float al = arow[ty*8 + i];
#pragma unroll
            for (int j = 0; j < 4; j++) acc[i][j] *= al;
        }
#pragma unroll 8
        for (int c = 0; c < 64; c++) {
            float a[8], b[4];
            *(float4*)&a[0] = *(const float4*)&St[c*68 + ty*8];
            *(float4*)&a[4] = *(const float4*)&St[c*68 + ty*8+4];
            *(float4*)&b[0] = *(const float4*)&Vs[c*68 + tx*4];
#pragma unroll
            for (int i = 0; i < 8; i++)
#pragma unroll
                for (int j = 0; j < 4; j++)
                    acc[i][j] = fmaf(a[i], b[j], acc[i][j]);
        }
    }

    // write [B, N, H, Dh]
    const int b = bh >> 4, h = bh & 15;
#pragma unroll
    for (int i = 0; i < 8; i++) {
        int r = ty * 8 + i;
        float linv = 1.f / lrow[r];
        int tok = q0 + r;
        float4 o4 = make_float4(acc[i][0]*linv, acc[i][1]*linv,
                                acc[i][2]*linv, acc[i][3]*linv);
        *(float4*)&g_ao[(((size_t)(b * 2048 + tok) * 16 + h) << 6) + tx*4] = o4;
    }
}

// ---------------------------------------------------------------------------
// Kernel C: out = attn_out @ proj_w^T + proj_b  (4096 x 1024 x 1024)
// ---------------------------------------------------------------------------
__global__ __launch_bounds__(256) void proj_kernel(
    const float* __restrict__ w, const float* __restrict__ bias,
    float* __restrict__ out)
{
    __shared__ float At[16][132];
    __shared__ float Bt[16][132];

    const int tid = threadIdx.x;
    const int tx  = tid & 15;
    const int ty  = tid >> 4;
    const int m0  = blockIdx.y * 128;
    const int n0  = blockIdx.x * 128;

    float acc[8][8];
#pragma unroll
    for (int i = 0; i < 8; i++)
#pragma unroll
        for (int j = 0; j < 8; j++) acc[i][j] = 0.f;

    const int lkq  = (tid & 3) * 4;
    const int lrow = tid >> 2;

    for (int k0 = 0; k0 < C_; k0 += 16) {
#pragma unroll
        for (int s = 0; s < 2; s++) {
            int row = lrow + s * 64;
            float4 a4 = *(const float4*)&g_ao[(size_t)(m0 + row) * C_ + k0 + lkq];
            At[lkq+0][row] = a4.x; At[lkq+1][row] = a4.y;
            At[lkq+2][row] = a4.z; At[lkq+3][row] = a4.w;
            float4 b4 = *(const float4*)&w[(size_t)(n0 + row) * C_ + k0 + lkq];
            Bt[lkq+0][row] = b4.x; Bt[lkq+1][row] = b4.y;
            Bt[lkq+2][row] = b4.z; Bt[lkq+3][row] = b4.w;
        }
        __syncthreads();
#pragma unroll
        for (int kk = 0; kk < 16; kk++) {
            float a[8], b[8];
            *(float4*)&a[0] = *(const float4*)&At[kk][ty*8];
            *(float4*)&a[4] = *(const float4*)&At[kk][ty*8+4];
            *(float4*)&b[0] = *(const float4*)&Bt[kk][tx*8];
            *(float4*)&b[4] = *(const float4*)&Bt[kk][tx*8+4];
#pragma unroll
            for (int i = 0; i < 8; i++)
#pragma unroll
                for (int j = 0; j < 8; j++)
                    acc[i][j] = fmaf(a[i], b[j], acc[i][j]);
        }
        __syncthreads();
    }

    float bb[8];
    *(float4*)&bb[0] = *(const float4*)&bias[n0 + tx*8];
    *(float4*)&bb[4] = *(const float4*)&bias[n0 + tx*8 + 4];
#pragma unroll
    for (int i = 0; i < 8; i++) {
        int m = m0 + ty * 8 + i;
        float o[8];
#pragma unroll
        for (int j = 0; j < 8; j++) o[j] = acc[i][j] + bb[j];
        float* dst = out + (size_t)m * C_ + n0 + tx*8;
        *(float4*)&dst[0] = *(const float4*)&o[0];
        *(float4*)&dst[4] = *(const float4*)&o[4];
    }
}

// ---------------------------------------------------------------------------
extern "C" void kernel_launch(void* const* d_in, const int* in_sizes, int n_in,
                              void* d_out, int out_size)
{
    const float* x      = (const float*)d_in[0];
    const int*   pos    = (const int*)  d_in[1];
    const float* qkv_w  = (const float*)d_in[2];
    const float* proj_w = (const float*)d_in[3];
    const float* proj_b = (const float*)d_in[4];
    float*       out    = (float*)d_out;

    // A: qkv + rope.  grid: 3072/128 n-tiles x 4096/128 m-tiles
    qkv_rope_kernel<<<dim3(24, 32), 256>>>(x, qkv_w, pos);

    // B: flash attention. 64-row q tiles x 32 head-batches. ~70KB dyn smem.
    const int attn_smem = (4 * 64 * 68 + 3 * 64) * (int)sizeof(float);
    cudaFuncSetAttribute(attn_kernel,
                         cudaFuncAttributeMaxDynamicSharedMemorySize, attn_smem);
    attn_kernel<<<dim3(32, 32), 128, attn_smem>>>();

    // C: output projection + bias
    proj_kernel<<<dim3(8, 32), 256>>>(proj_w, proj_b, out);
}

// round 3
// speedup vs baseline: 1.7516x; 1.7516x over previous
#include <cuda_runtime.h>
#include <math.h>
#include <stdint.h>

#define B_  2
#define N_  2048
#define C_  1024
#define H_  16
#define DH_ 64
#define M_  (B_*N_)
#define BH_ (B_*H_)

__device__ float g_q [BH_ * N_ * DH_];
__device__ float g_k [BH_ * N_ * DH_];
__device__ float g_v [BH_ * N_ * DH_];
__device__ float g_ao[M_ * C_];

__constant__ float c_invf[16] = {
    1.0f, 0.7498942093324559f, 0.5623413251903491f, 0.4216965034285822f,
    0.31622776601683794f, 0.23713737056616552f, 0.1778279410038923f,
    0.13335214321633237f, 0.1f, 0.07498942093324558f, 0.05623413251903491f,
    0.04216965034285822f, 0.031622776601683794f, 0.023713737056616552f,
    0.01778279410038923f, 0.013335214321633237f
};

// ---- tf32 helpers (Ampere-era PTX: compiles for plain sm_103 target) ----
__device__ __forceinline__ float tf32r(float x) {
    uint32_t u;
    asm("cvt.rna.tf32.f32 %0, %1;" : "=r"(u) : "f"(x));
    return __uint_as_float(u);
}
__device__ __forceinline__ void mma8(float* d, const uint32_t* a, const uint32_t* b) {
    asm volatile(
        "mma.sync.aligned.m16n8k8.row.col.f32.tf32.tf32.f32 "
        "{%0,%1,%2,%3}, {%4,%5,%6,%7}, {%8,%9}, {%0,%1,%2,%3};"
        : "+f"(d[0]), "+f"(d[1]), "+f"(d[2]), "+f"(d[3])
        : "r"(a[0]), "r"(a[1]), "r"(a[2]), "r"(a[3]), "r"(b[0]), "r"(b[1]));
}

// ===========================================================================
// GEMM mainloop: acc[4][4][4] (warp 64x32) = A[m0:128,:1024] @ Bw[n0:128,:1024]^T
// tf32x2 (3 passes). 256 threads = 8 warps (2m x 4n). BK=16. stride-20 smem.
// ===========================================================================
#define SA 20
__device__ __forceinline__ void gemm_ml(
    const float* __restrict__ A, const float* __restrict__ Bw,
    int m0, int n0, float* sAh, float* sAl, float* sBh, float* sBl,
    float acc[4][4][4])
{
    const int tid = threadIdx.x, lane = tid & 31, wid = tid >> 5;
    const int gid = lane >> 2, tig = lane & 3;
    const int wm = (wid >> 2) * 64, wn = (wid & 3) * 32;
    const uint32_t *uAh = (const uint32_t*)sAh, *uAl = (const uint32_t*)sAl;
    const uint32_t *uBh = (const uint32_t*)sBh, *uBl = (const uint32_t*)sBl;

    for (int it = 0; it < 64; ++it) {
        const int k0 = it * 16;
#pragma unroll
        for (int s = 0; s < 2; ++s) {
            int c = tid + s * 256, row = c >> 2, q = (c & 3) * 4;
            float4 va = *(const float4*)(A + (size_t)(m0 + row) * 1024 + k0 + q);
            float4 vh, vl;
            vh.x = tf32r(va.x); vl.x = tf32r(va.x - vh.x);
            vh.y = tf32r(va.y); vl.y = tf32r(va.y - vh.y);
            vh.z = tf32r(va.z); vl.z = tf32r(va.z - vh.z);
            vh.w = tf32r(va.w); vl.w = tf32r(va.w - vh.w);
            *(float4*)(sAh + row * SA + q) = vh;
            *(float4*)(sAl + row * SA + q) = vl;
            float4 vb = *(const float4*)(Bw + (size_t)(n0 + row) * 1024 + k0 + q);
            vh.x = tf32r(vb.x); vl.x = tf32r(vb.x - vh.x);
            vh.y = tf32r(vb.y); vl.y = tf32r(vb.y - vh.y);
            vh.z = tf32r(vb.z); vl.z = tf32r(vb.z - vh.z);
            vh.w = tf32r(vb.w); vl.w = tf32r(vb.w - vh.w);
            *(float4*)(sBh + row * SA + q) = vh;
            *(float4*)(sBl + row * SA + q) = vl;
        }
        __syncthreads();
#pragma unroll
        for (int ks = 0; ks < 2; ++ks) {
            uint32_t ah[4][4], al[4][4], bh[4][2], bl[4][2];
#pragma unroll
            for (int i = 0; i < 4; ++i) {
                int ba = (wm + i * 16 + gid) * SA + ks * 8 + tig;
                ah[i][0] = uAh[ba];            ah[i][1] = uAh[ba + 8 * SA];
                ah[i][2] = uAh[ba + 4];        ah[i][3] = uAh[ba + 8 * SA + 4];
                al[i][0] = uAl[ba];            al[i][1] = uAl[ba + 8 * SA];
                al[i][2] = uAl[ba + 4];        al[i][3] = uAl[ba + 8 * SA + 4];
            }
#pragma unroll
            for (int j = 0; j < 4; ++j) {
                int bb = (wn + j * 8 + gid) * SA + ks * 8 + tig;
                bh[j][0] = uBh[bb]; bh[j][1] = uBh[bb + 4];
                bl[j][0] = uBl[bb]; bl[j][1] = uBl[bb + 4];
            }
#pragma unroll
            for (int i = 0; i < 4; ++i)
#pragma unroll
                for (int j = 0; j < 4; ++j) {
                    mma8(acc[i][j], ah[i], bh[j]);
                    mma8(acc[i][j], ah[i], bl[j]);
                    mma8(acc[i][j], al[i], bh[j]);
                }
        }
        __syncthreads();
    }
}

// ---------------------------------------------------------------------------
// Kernel A: qkv GEMM + RoPE + scatter. Grid (24, 32), 256 threads.
// ---------------------------------------------------------------------------
__global__ __launch_bounds__(256) void qkv_mma_kernel(
    const float* __restrict__ x, const float* __restrict__ w,
    const int* __restrict__ pos)
{
    __shared__ float sAh[128*SA], sAl[128*SA], sBh[128*SA], sBl[128*SA];
    const int tid = threadIdx.x, lane = tid & 31, wid = tid >> 5;
    const int gid = lane >> 2, tig = lane & 3;
    const int wm = (wid >> 2) * 64, wn = (wid & 3) * 32;
    const int m0 = blockIdx.y * 128, n0 = blockIdx.x * 128;

    float acc[4][4][4];
#pragma unroll
    for (int i = 0; i < 4; ++i)
#pragma unroll
        for (int j = 0; j < 4; ++j)
#pragma unroll
            for (int c = 0; c < 4; ++c) acc[i][j][c] = 0.f;

    gemm_ml(x, w, m0, n0, sAh, sAl, sBh, sBl, acc);

    const int which = n0 >> 10;                       // 0=q 1=k 2=v
    const int h  = (((n0 & 1023) + wn) >> 6);
    const int db = wn & 32;
    float* dst = (which == 0) ? g_q : (which == 1) ? g_k : g_v;

#pragma unroll
    for (int i = 0; i < 4; ++i) {
        int mA = m0 + wm + i * 16 + gid;
        int mB = mA + 8;
        float* oA = dst + (((size_t)((mA >> 11) * 16 + h) * 2048 + (mA & 2047)) << 6);
        float* oB = dst + (((size_t)((mB >> 11) * 16 + h) * 2048 + (mB & 2047)) << 6);
        if (which == 2) {
#pragma unroll
            for (int j = 0; j < 4; ++j) {
                int d = db + j * 8 + 2 * tig;
                *(float2*)(oA + d) = make_float2(acc[i][j][0], acc[i][j][1]);
                *(float2*)(oB + d) = make_float2(acc[i][j][2], acc[i][j][3]);
            }
        } else {
            int2 pA = ((const int2*)pos)[mA];
            int2 pB = ((const int2*)pos)[mB];
            float pa = db ? (float)pA.y : (float)pA.x;
            float pb = db ? (float)pB.y : (float)pB.x;
#pragma unroll
            for (int j = 0; j < 2; ++j) {
                int dd = j * 8 + 2 * tig;
                float s0a,c0a,s1a,c1a,s0b,c0b,s1b,c1b;
                sincosf(pa * c_invf[dd],     &s0a, &c0a);
                sincosf(pa * c_invf[dd + 1], &s1a, &c1a);
                sincosf(pb * c_invf[dd],     &s0b, &c0b);
                sincosf(pb * c_invf[dd + 1], &s1b, &c1b);
                float y10 = acc[i][j][0], y20 = acc[i][j+2][0];
                float y11 = acc[i][j][1], y21 = acc[i][j+2][1];
                *(float2*)(oA + db + dd)      = make_float2(y10*c0a - y20*s0a, y11*c1a - y21*s1a);
                *(float2*)(oA + db + dd + 16) = make_float2(y10*s0a + y20*c0a, y11*s1a + y21*c1a);
                float z10 = acc[i][j][2], z20 = acc[i][j+2][2];
                float z11 = acc[i][j][3], z21 = acc[i][j+2][3];
                *(float2*)(oB + db + dd)      = make_float2(z10*c0b - z20*s0b, z11*c1b - z21*s1b);
                *(float2*)(oB + db + dd + 16) = make_float2(z10*s0b + z20*c0b, z11*s1b + z21*c1b);
            }
        }
    }
}

// ---------------------------------------------------------------------------
// Kernel C: out = g_ao @ proj_w^T + bias. Grid (8, 32), 256 threads.
// ---------------------------------------------------------------------------
__global__ __launch_bounds__(256) void proj_mma_kernel(
    const float* __restrict__ w, const float* __restrict__ bias,
    float* __restrict__ out)
{
    __shared__ float sAh[128*SA], sAl[128*SA], sBh[128*SA], sBl[128*SA];
    const int tid = threadIdx.x, lane = tid & 31, wid = tid >> 5;
    const int gid = lane >> 2, tig = lane & 3;
    const int wm = (wid >> 2) * 64, wn = (wid & 3) * 32;
    const int m0 = blockIdx.y * 128, n0 = blockIdx.x * 128;

    float acc[4][4][4];
#pragma unroll
    for (int i = 0; i < 4; ++i)
#pragma unroll
        for (int j = 0; j < 4; ++j)
#pragma unroll
            for (int c = 0; c < 4; ++c) acc[i][j][c] = 0.f;

    gemm_ml(g_ao, w, m0, n0, sAh, sAl, sBh, sBl, acc);

#pragma unroll
    for (int i = 0; i < 4; ++i) {
        int mA = m0 + wm + i * 16 + gid;
#pragma unroll
        for (int j = 0; j < 4; ++j) {
            int n = n0 + wn + j * 8 + 2 * tig;
            float b0 = bias[n], b1 = bias[n + 1];
            *(float2*)(out + (size_t)mA * 1024 + n) =
                make_float2(acc[i][j][0] + b0, acc[i][j][1] + b1);
            *(float2*)(out + (size_t)(mA + 8) * 1024 + n) =
                make_float2(acc[i][j][2] + b0, acc[i][j][3] + b1);
        }
    }
}

// ---------------------------------------------------------------------------
// Kernel B: flash attention with tf32 mma. One CTA = 64 q-rows of one (b,h).
// 4 warps x 16 q-rows. QK^T tf32x2, PV tf32x1, register online softmax.
// ---------------------------------------------------------------------------
#define SQ 68
#define SV 72
#define ATTN_SMEM ((4*64*SQ + 64*SV + 4*16*SQ) * 4)

__global__ __launch_bounds__(128) void attn_mma_kernel()
{
    extern __shared__ float sm[];
    float* sQh = sm;
    float* sQl = sQh + 64 * SQ;
    float* sKh = sQl + 64 * SQ;
    float* sKl = sKh + 64 * SQ;
    float* sV  = sKl + 64 * SQ;
    float* sP  = sV  + 64 * SV;

    const int tid = threadIdx.x, lane = tid & 31, wid = tid >> 5;
    const int gid = lane >> 2, tig = lane & 3;
    const int bh = blockIdx.y, q0 = blockIdx.x * 64;

    const float* Qg = g_q + ((size_t)bh * N_ + q0) * DH_;
    const float* Kg = g_k + (size_t)bh * N_ * DH_;
    const float* Vg = g_v + (size_t)bh * N_ * DH_;

    // Q tile (scaled by 1/8, split hi/lo)
#pragma unroll
    for (int s = 0; s < 8; ++s) {
        int c = tid + s * 128, row = c >> 4, q = (c & 15) * 4;
        float4 v = *(const float4*)(Qg + row * 64 + q);
        v.x *= 0.125f; v.y *= 0.125f; v.z *= 0.125f; v.w *= 0.125f;
        float4 vh, vl;
        vh.x = tf32r(v.x); vl.x = tf32r(v.x - vh.x);
        vh.y = tf32r(v.y); vl.y = tf32r(v.y - vh.y);
        vh.z = tf32r(v.z); vl.z = tf32r(v.z - vh.z);
        vh.w = tf32r(v.w); vl.w = tf32r(v.w - vh.w);
        *(float4*)(sQh + row * SQ + q) = vh;
        *(float4*)(sQl + row * SQ + q) = vl;
    }

    float o[8][4];
#pragma unroll
    for (int j = 0; j < 8; ++j)
#pragma unroll
        for (int c = 0; c < 4; ++c) o[j][c] = 0.f;
    float m0r = -1e30f, m1r = -1e30f, l0 = 0.f, l1 = 0.f;

    const uint32_t *uQh = (const uint32_t*)sQh, *uQl = (const uint32_t*)sQl;
    const uint32_t *uKh = (const uint32_t*)sKh, *uKl = (const uint32_t*)sKl;
    const uint32_t *uV  = (const uint32_t*)sV;
    float* wP = sP + wid * 16 * SQ;
    const uint32_t* uP = (const uint32_t*)wP;

    for (int kv0 = 0; kv0 < N_; kv0 += 64) {
        __syncthreads();
#pragma unroll
        for (int s = 0; s < 8; ++s) {
            int c = tid + s * 128, row = c >> 4, q = (c & 15) * 4;
            float4 k4 = *(const float4*)(Kg + (size_t)(kv0 + row) * 64 + q);
            float4 vh, vl;
            vh.x = tf32r(k4.x); vl.x = tf32r(k4.x - vh.x);
            vh.y = tf32r(k4.y); vl.y = tf32r(k4.y - vh.y);
            vh.z = tf32r(k4.z); vl.z = tf32r(k4.z - vh.z);
            vh.w = tf32r(k4.w); vl.w = tf32r(k4.w - vh.w);
            *(float4*)(sKh + row * SQ + q) = vh;
            *(float4*)(sKl + row * SQ + q) = vl;
            float4 v4 = *(const float4*)(Vg + (size_t)(kv0 + row) * 64 + q);
            v4.x = tf32r(v4.x); v4.y = tf32r(v4.y);
            v4.z = tf32r(v4.z); v4.w = tf32r(v4.w);
            *(float4*)(sV + row * SV + q) = v4;
        }
        __syncthreads();

        // S = (Q/8) K^T, tf32x2
        float s8[8][4];
#pragma unroll
        for (int j = 0; j < 8; ++j)
#pragma unroll
            for (int c = 0; c < 4; ++c) s8[j][c] = 0.f;
#pragma unroll
        for (int kc = 0; kc < 8; ++kc) {
            uint32_t ah[4], al[4];
            int ba = (wid * 16 + gid) * SQ + kc * 8 + tig;
            ah[0] = uQh[ba];     ah[1] = uQh[ba + 8 * SQ];
            ah[2] = uQh[ba + 4]; ah[3] = uQh[ba + 8 * SQ + 4];
            al[0] = uQl[ba];     al[1] = uQl[ba + 8 * SQ];
            al[2] = uQl[ba + 4]; al[3] = uQl[ba + 8 * SQ + 4];
#pragma unroll
            for (int j = 0; j < 8; ++j) {
                int bb = (j * 8 + gid) * SQ + kc * 8 + tig;
                uint32_t kh2[2] = { uKh[bb], uKh[bb + 4] };
                uint32_t kl2[2] = { uKl[bb], uKl[bb + 4] };
                mma8(s8[j], ah, kh2);
                mma8(s8[j], ah, kl2);
                mma8(s8[j], al, kh2);
            }
        }

        // online softmax (rows gid, gid+8)
        float mx0 = -1e30f, mx1 = -1e30f;
#pragma unroll
        for (int j = 0; j < 8; ++j) {
            mx0 = fmaxf(mx0, fmaxf(s8[j][0], s8[j][1]));
            mx1 = fmaxf(mx1, fmaxf(s8[j][2], s8[j][3]));
        }
        mx0 = fmaxf(mx0, __shfl_xor_sync(0xffffffffu, mx0, 1));
        mx0 = fmaxf(mx0, __shfl_xor_sync(0xffffffffu, mx0, 2));
        mx1 = fmaxf(mx1, __shfl_xor_sync(0xffffffffu, mx1, 1));
        mx1 = fmaxf(mx1, __shfl_xor_sync(0xffffffffu, mx1, 2));
        float mn0 = fmaxf(m0r, mx0), mn1 = fmaxf(m1r, mx1);
        float al0 = __expf(m0r - mn0), al1 = __expf(m1r - mn1);
        m0r = mn0; m1r = mn1;
        float sum0 = 0.f, sum1 = 0.f;
#pragma unroll
        for (int j = 0; j < 8; ++j) {
            s8[j][0] = __expf(s8[j][0] - mn0); sum0 += s8[j][0];
            s8[j][1] = __expf(s8[j][1] - mn0); sum0 += s8[j][1];
            s8[j][2] = __expf(s8[j][2] - mn1); sum1 += s8[j][2];
            s8[j][3] = __expf(s8[j][3] - mn1); sum1 += s8[j][3];
        }
        sum0 += __shfl_xor_sync(0xffffffffu, sum0, 1);
        sum0 += __shfl_xor_sync(0xffffffffu, sum0, 2);
        sum1 += __shfl_xor_sync(0xffffffffu, sum1, 1);
        sum1 += __shfl_xor_sync(0xffffffffu, sum1, 2);
        l0 = l0 * al0 + sum0;
        l1 = l1 * al1 + sum1;
#pragma unroll
        for (int j = 0; j < 8; ++j) {
            o[j][0] *= al0; o[j][1] *= al0;
            o[j][2] *= al1; o[j][3] *= al1;
        }

        // stash P (tf32-rounded) in per-warp smem
#pragma unroll
        for (int j = 0; j < 8; ++j) {
            *(float2*)(wP + gid * SQ + j * 8 + 2 * tig) =
                make_float2(tf32r(s8[j][0]), tf32r(s8[j][1]));
            *(float2*)(wP + (gid + 8) * SQ + j * 8 + 2 * tig) =
                make_float2(tf32r(s8[j][2]), tf32r(s8[j][3]));
        }
        __syncwarp();

        // O += P V  (single tf32)
#pragma unroll
        for (int kc = 0; kc < 8; ++kc) {
            uint32_t pa[4];
            int pb = gid * SQ + kc * 8 + tig;
            pa[0] = uP[pb];     pa[1] = uP[pb + 8 * SQ];
            pa[2] = uP[pb + 4]; pa[3] = uP[pb + 8 * SQ + 4];
#pragma unroll
            for (int j = 0; j < 8; ++j) {
                int vb = (kc * 8 + tig) * SV + j * 8 + gid;
                uint32_t vv[2] = { uV[vb], uV[vb + 4 * SV] };
                mma8(o[j], pa, vv);
            }
        }
        __syncwarp();
    }

    const float linv0 = 1.f / l0, linv1 = 1.f / l1;
    const int b = bh >> 4, h = bh & 15;
    const int tok0 = q0 + wid * 16 + gid, tok1 = tok0 + 8;
    float* oA = g_ao + (((size_t)(b * 2048 + tok0) * 16 + h) << 6);
    float* oB = g_ao + (((size_t)(b * 2048 + tok1) * 16 + h) << 6);
#pragma unroll
    for (int j = 0; j < 8; ++j) {
        int d = j * 8 + 2 * tig;
        *(float2*)(oA + d) = make_float2(o[j][0] * linv0, o[j][1] * linv0);
        *(float2*)(oB + d) = make_float2(o[j][2] * linv1, o[j][3] * linv1);
    }
}

// ---------------------------------------------------------------------------
extern "C" void kernel_launch(void* const* d_in, const int* in_sizes, int n_in,
                              void* d_out, int out_size)
{
    const float* x      = (const float*)d_in[0];
    const int*   pos    = (const int*)  d_in[1];
    const float* qkv_w  = (const float*)d_in[2];
    const float* proj_w = (const float*)d_in[3];
    const float* proj_b = (const float*)d_in[4];
    float*       out    = (float*)d_out;

    qkv_mma_kernel<<<dim3(24, 32), 256>>>(x, qkv_w, pos);

    cudaFuncSetAttribute(attn_mma_kernel,
                         cudaFuncAttributeMaxDynamicSharedMemorySize, ATTN_SMEM);
    attn_mma_kernel<<<dim3(32, 32), 128, ATTN_SMEM>>>();

    proj_mma_kernel<<<dim3(8, 32), 256>>>(proj_w, proj_b, out);
}